// round 16
// baseline (speedup 1.0000x reference)
#include <cuda_runtime.h>
#include <cuda_fp16.h>
#include <math.h>
#include <stdint.h>

// ---------------- problem constants ----------------
#define BB        2
#define SS        4096
#define HH        2048
#define NHEADS    16
#define HDIM      128
#define KSEL      128
#define BAND      256
#define NROWS     (BB*SS)            // 8192
#define NBH       (BB*NHEADS)        // 32
#define ROWHID    ((long)NROWS*HH)   // 16777216
#define WN        ((long)HH*HH)      // 4194304
#define SELN      (NBH*KSEL*HDIM)    // 524288

// ---------------- scratch (device globals; no allocs allowed) ----------------
__device__ float  gScores[NBH*SS];
__device__ float  gS256[NBH*BAND];
__device__ int    gIdx[NBH*KSEL];
__device__ int    gBand[NBH*BAND];
__device__ int    gNpos[NBH];
__device__ __half gXhi[ROWHID];
__device__ __half gXlo[ROWHID];
__device__ __half gQhi[ROWHID];
__device__ __half gOhi[ROWHID];
__device__ __half gWBig[2*WN];       // rows 0..2047: wq_hi ; rows 2048..4095: Wc_hi
__device__ __half gWk[WN];
__device__ __half gWv[WN];
__device__ __half gWo[WN];
__device__ __half gWchi[WN];
__device__ __half gWclo[WN];
__device__ __half gKselh[SELN];
__device__ __half gVselTh[SELN];

// =================== helpers ===================
__device__ __forceinline__ uint32_t smem_u32(const void* p) {
    uint32_t a;
    asm("{ .reg .u64 t; cvta.to.shared.u64 t, %1; cvt.u32.u64 %0, t; }" : "=r"(a) : "l"(p));
    return a;
}
__device__ __forceinline__ void cp16(uint32_t dst, const void* src) {
    asm volatile("cp.async.cg.shared.global [%0], [%1], 16;" :: "r"(dst), "l"(src));
}
__device__ __forceinline__ void cp_commit() {
    asm volatile("cp.async.commit_group;" ::: "memory");
}
template<int N>
__device__ __forceinline__ void cp_wait() {
    asm volatile("cp.async.wait_group %0;" :: "n"(N) : "memory");
}
__device__ __forceinline__ void mma16816(float* c, const uint32_t* a, uint32_t b0, uint32_t b1) {
    asm volatile(
        "mma.sync.aligned.m16n8k16.row.col.f32.f16.f16.f32 "
        "{%0,%1,%2,%3}, {%4,%5,%6,%7}, {%8,%9}, {%0,%1,%2,%3};"
        : "+f"(c[0]), "+f"(c[1]), "+f"(c[2]), "+f"(c[3])
        : "r"(a[0]), "r"(a[1]), "r"(a[2]), "r"(a[3]), "r"(b0), "r"(b1));
}

// =================== vectorized splits (8 elems / thread) ===================
__device__ __forceinline__ void cvt1x8(const float* __restrict__ s, __half* __restrict__ d, long g) {
    const float4* sp = (const float4*)s + g * 2;
    float4 a = sp[0], b = sp[1];
    __half2 h0 = __halves2half2(__float2half_rn(a.x), __float2half_rn(a.y));
    __half2 h1 = __halves2half2(__float2half_rn(a.z), __float2half_rn(a.w));
    __half2 h2 = __halves2half2(__float2half_rn(b.x), __float2half_rn(b.y));
    __half2 h3 = __halves2half2(__float2half_rn(b.z), __float2half_rn(b.w));
    uint4 o;
    o.x = *(uint32_t*)&h0; o.y = *(uint32_t*)&h1;
    o.z = *(uint32_t*)&h2; o.w = *(uint32_t*)&h3;
    ((uint4*)d)[g] = o;
}
__device__ __forceinline__ void cvt2x8(const float* __restrict__ s,
                                       __half* __restrict__ dh, __half* __restrict__ dl, long g) {
    const float4* sp = (const float4*)s + g * 2;
    float4 a = sp[0], b = sp[1];
    float f[8] = {a.x, a.y, a.z, a.w, b.x, b.y, b.z, b.w};
    uint32_t hw[4], lw[4];
#pragma unroll
    for (int j = 0; j < 4; j++) {
        __half h0 = __float2half_rn(f[2 * j]);
        __half h1 = __float2half_rn(f[2 * j + 1]);
        __half l0 = __float2half_rn((f[2 * j] - __half2float(h0)) * 64.0f);
        __half l1 = __float2half_rn((f[2 * j + 1] - __half2float(h1)) * 64.0f);
        __half2 hh = __halves2half2(h0, h1);
        __half2 ll = __halves2half2(l0, l1);
        hw[j] = *(uint32_t*)&hh;
        lw[j] = *(uint32_t*)&ll;
    }
    ((uint4*)dh)[g] = make_uint4(hw[0], hw[1], hw[2], hw[3]);
    ((uint4*)dl)[g] = make_uint4(lw[0], lw[1], lw[2], lw[3]);
}

__global__ void splitX(const float* __restrict__ s, __half* __restrict__ hi,
                       __half* __restrict__ lo, long n8)
{
    long i = (long)blockIdx.x * blockDim.x + threadIdx.x;
    if (i >= n8) return;
    cvt2x8(s, hi, lo, i);
}

__global__ void splitW(const float* __restrict__ wq, const float* __restrict__ wk,
                       const float* __restrict__ wv, const float* __restrict__ wo,
                       __half* __restrict__ qbig, __half* __restrict__ k,
                       __half* __restrict__ v, __half* __restrict__ o)
{
    long i = (long)blockIdx.x * blockDim.x + threadIdx.x;
    if (i >= WN / 8) return;
    cvt1x8(wq, qbig, i);
    cvt1x8(wk, k, i);
    cvt1x8(wv, v, i);
    cvt1x8(wo, o, i);
}

// =================== Wc = sw1 @ wk_head (composed score weight) =============
__global__ __launch_bounds__(256) void wc_make(const float* __restrict__ sw1,
                                               const float* __restrict__ wk,
                                               __half* __restrict__ wchi,
                                               __half* __restrict__ wclo,
                                               __half* __restrict__ wbig)
{
    __shared__ float wks[128][33];
    const int h  = blockIdx.x >> 6;
    const int cb = (blockIdx.x & 63) * 32;
    const int t  = threadIdx.x;
#pragma unroll
    for (int e = 0; e < 16; e++) {
        int idx = t + e * 256;
        int k = idx >> 5, c = idx & 31;
        wks[k][c] = wk[(long)(h * 128 + k) * HH + cb + c];
    }
    __syncthreads();
    const int ip = t >> 1;
    const int cs = (t & 1) * 16;
    const float* s1r = sw1 + ip * HDIM;
    float acc[16];
#pragma unroll
    for (int j = 0; j < 16; j++) acc[j] = 0.f;
    for (int k = 0; k < 128; k++) {
        float s = s1r[k];
#pragma unroll
        for (int j = 0; j < 16; j++) acc[j] += s * wks[k][cs + j];
    }
    long base  = (long)(h * 128 + ip) * HH + cb + cs;
    long baseb = (long)(HH + h * 128 + ip) * HH + cb + cs;
#pragma unroll
    for (int j = 0; j < 16; j++) {
        __half hh = __float2half_rn(acc[j]);
        wchi[base + j] = hh;
        wbig[baseb + j] = hh;
        wclo[base + j] = __float2half_rn((acc[j] - __half2float(hh)) * 64.0f);
    }
}

#define SKW 40
#define PLANE_B (128 * SKW * 2)      // 10240 bytes
#define PLANE_A64 (64 * SKW * 2)     // 5120 bytes
#define PLANE_BW (256 * SKW * 2)     // 20480 bytes

// =================== HMMA split GEMM (128x128 tile, 256 thr) ================
// NPROD 3/1. EMIT: 2 fp16 hi; 3 fused score head.
// IDX: 0 = none; 1 = A rows indexed into X (Ahi/Alo are full X arrays);
//      2 = B rows indexed into X (Bhi is full X array).
template<int NPROD, int EMIT, int IDX>
__global__ __launch_bounds__(256, 1) void hgemm(
    const __half* __restrict__ Ahi, const __half* __restrict__ Alo,
    const __half* __restrict__ Bhi, const __half* __restrict__ Blo,
    float* __restrict__ Cf, __half* __restrict__ Chi,
    int lda, int ldb, int ldc,
    long strAb, long strAh, long strBb, long strBh, long strCb, long strCh,
    int Kd, float alpha,
    const float* __restrict__ sb1g, const float* __restrict__ sw2g,
    const float* __restrict__ sb2g,
    const int* __restrict__ idxp, int idxN)
{
    constexpr int NPL = (NPROD == 3) ? 4 : (NPROD == 2 ? 3 : 2);
    constexpr int STG = NPL * PLANE_B;
    extern __shared__ char smem[];
    const uint32_t smb = smem_u32(smem);
    const int tid  = threadIdx.x;
    const int wid  = tid >> 5;
    const int lane = tid & 31;
    const int wm   = wid & 1;
    const int wn   = wid >> 1;
    const int qrow = lane >> 2;
    const int qk   = (lane & 3) * 2;

    const int z = blockIdx.z, zb = z >> 4, zh = z & 15;
    const long m0 = (long)blockIdx.y * 128;
    const long n0 = (long)blockIdx.x * 128;

    const __half* pg[4];
    int pld[4];
    pg[0] = Ahi + zb * strAb + zh * strAh + m0 * lda;  pld[0] = lda;
    pg[1] = Bhi + zb * strBb + zh * strBh + n0 * ldb;  pld[1] = ldb;
    pg[2] = (NPROD >= 2) ? (Blo + zb * strBb + zh * strBh + n0 * ldb) : pg[1];
    pld[2] = ldb;
    pg[3] = (NPROD == 3) ? (Alo + zb * strAb + zh * strAh + m0 * lda) : pg[0];
    pld[3] = lda;

    const int r0 = tid >> 2, s0 = tid & 3;
    const int r1 = r0 + 64;

    // precompute per-thread row base pointers (supports indexed X rows)
    const __half* rp[4][2];
#pragma unroll
    for (int p = 0; p < NPL; p++) {
        const bool isA = (p == 0 || p == 3);
#pragma unroll
        for (int ri = 0; ri < 2; ri++) {
            const int r = (ri == 0) ? r0 : r1;
            if (IDX == 1 && isA) {
                int grow = idxp[(long)z * idxN + m0 + r];
                const __half* base = (p == 0) ? Ahi : Alo;
                rp[p][ri] = base + ((long)zb * SS + grow) * lda;
            } else if (IDX == 2 && !isA) {
                int grow = idxp[(long)z * idxN + n0 + r];
                const __half* base = (p == 1) ? Bhi : Blo;
                rp[p][ri] = base + ((long)zb * SS + grow) * ldb;
            } else {
                rp[p][ri] = pg[p] + (long)r * pld[p];
            }
        }
    }

    float acc[4][4][4], axx[4][4][4];
#pragma unroll
    for (int i = 0; i < 4; i++)
#pragma unroll
        for (int j = 0; j < 4; j++)
#pragma unroll
            for (int r = 0; r < 4; r++) { acc[i][j][r] = 0.f; axx[i][j][r] = 0.f; }

    const int NC = Kd / 32;

#pragma unroll
    for (int p = 0; p < NPL; p++) {
        cp16(smb + p * PLANE_B + r0 * (SKW * 2) + s0 * 16, rp[p][0] + s0 * 8);
        cp16(smb + p * PLANE_B + r1 * (SKW * 2) + s0 * 16, rp[p][1] + s0 * 8);
    }
    cp_commit();

    for (int ch = 0; ch < NC; ch++) {
        const int st = ch & 1;
        if (ch + 1 < NC) {
            const int k0 = (ch + 1) * 32;
            const uint32_t sb = smb + (st ^ 1) * STG;
#pragma unroll
            for (int p = 0; p < NPL; p++) {
                cp16(sb + p * PLANE_B + r0 * (SKW * 2) + s0 * 16, rp[p][0] + k0 + s0 * 8);
                cp16(sb + p * PLANE_B + r1 * (SKW * 2) + s0 * 16, rp[p][1] + k0 + s0 * 8);
            }
            cp_commit();
            cp_wait<1>();
        } else {
            cp_wait<0>();
        }
        __syncthreads();

        const uint32_t* pAh = (const uint32_t*)(smem + st * STG + 0 * PLANE_B);
        const uint32_t* pBh = (const uint32_t*)(smem + st * STG + 1 * PLANE_B);
        const uint32_t* pBl = (const uint32_t*)(smem + st * STG + 2 * PLANE_B);
        const uint32_t* pAl = (const uint32_t*)(smem + st * STG + 3 * PLANE_B);

#pragma unroll
        for (int ks = 0; ks < 2; ks++) {
            const int kb = ks * 16;
            uint32_t af[4][4], bf[4][2];
#pragma unroll
            for (int mt = 0; mt < 4; mt++) {
                const int mr = wm * 64 + mt * 16 + qrow;
                af[mt][0] = pAh[(mr * SKW + kb + qk) >> 1];
                af[mt][1] = pAh[((mr + 8) * SKW + kb + qk) >> 1];
                af[mt][2] = pAh[(mr * SKW + kb + qk + 8) >> 1];
                af[mt][3] = pAh[((mr + 8) * SKW + kb + qk + 8) >> 1];
            }
#pragma unroll
            for (int nt = 0; nt < 4; nt++) {
                const int nr = wn * 32 + nt * 8 + qrow;
                bf[nt][0] = pBh[(nr * SKW + kb + qk) >> 1];
                bf[nt][1] = pBh[(nr * SKW + kb + qk + 8) >> 1];
            }
#pragma unroll
            for (int mt = 0; mt < 4; mt++)
#pragma unroll
                for (int nt = 0; nt < 4; nt++)
                    mma16816(acc[mt][nt], af[mt], bf[nt][0], bf[nt][1]);
            if (NPROD >= 2) {
                uint32_t bl[4][2];
#pragma unroll
                for (int nt = 0; nt < 4; nt++) {
                    const int nr = wn * 32 + nt * 8 + qrow;
                    bl[nt][0] = pBl[(nr * SKW + kb + qk) >> 1];
                    bl[nt][1] = pBl[(nr * SKW + kb + qk + 8) >> 1];
                }
#pragma unroll
                for (int mt = 0; mt < 4; mt++)
#pragma unroll
                    for (int nt = 0; nt < 4; nt++)
                        mma16816(axx[mt][nt], af[mt], bl[nt][0], bl[nt][1]);
            }
            if (NPROD == 3) {
#pragma unroll
                for (int mt = 0; mt < 4; mt++) {
                    const int mr = wm * 64 + mt * 16 + qrow;
                    af[mt][0] = pAl[(mr * SKW + kb + qk) >> 1];
                    af[mt][1] = pAl[((mr + 8) * SKW + kb + qk) >> 1];
                    af[mt][2] = pAl[(mr * SKW + kb + qk + 8) >> 1];
                    af[mt][3] = pAl[((mr + 8) * SKW + kb + qk + 8) >> 1];
                }
#pragma unroll
                for (int mt = 0; mt < 4; mt++)
#pragma unroll
                    for (int nt = 0; nt < 4; nt++)
                        mma16816(axx[mt][nt], af[mt], bf[nt][0], bf[nt][1]);
            }
        }
        __syncthreads();
    }

    float* cs = (float*)smem;   // [128][132]
    float* sb1s = (float*)(smem + 128 * 132 * 4);
    float* sw2s = sb1s + 128;
    const float inv64 = 1.0f / 64.0f;
#pragma unroll
    for (int mt = 0; mt < 4; mt++) {
#pragma unroll
        for (int nt = 0; nt < 4; nt++) {
            const int r = wm * 64 + mt * 16 + qrow;
            const int c = wn * 32 + nt * 8 + (lane & 3) * 2;
            if (NPROD >= 2) {
                cs[r * 132 + c]           = alpha * (acc[mt][nt][0] + axx[mt][nt][0] * inv64);
                cs[r * 132 + c + 1]       = alpha * (acc[mt][nt][1] + axx[mt][nt][1] * inv64);
                cs[(r + 8) * 132 + c]     = alpha * (acc[mt][nt][2] + axx[mt][nt][2] * inv64);
                cs[(r + 8) * 132 + c + 1] = alpha * (acc[mt][nt][3] + axx[mt][nt][3] * inv64);
            } else {
                cs[r * 132 + c]           = alpha * acc[mt][nt][0];
                cs[r * 132 + c + 1]       = alpha * acc[mt][nt][1];
                cs[(r + 8) * 132 + c]     = alpha * acc[mt][nt][2];
                cs[(r + 8) * 132 + c + 1] = alpha * acc[mt][nt][3];
            }
        }
    }
    if (EMIT == 3) {
        if (tid < 128) sb1s[tid] = sb1g[tid];
        else           sw2s[tid - 128] = sw2g[tid - 128];
    }
    __syncthreads();

    const int row = tid >> 1;
    const int hf  = tid & 1;
    if (EMIT == 3) {
        const float* crow = cs + row * 132 + hf * 64;
        float s = 0.f;
#pragma unroll
        for (int i = 0; i < 64; i++)
            s += fmaxf(crow[i] + sb1s[hf * 64 + i], 0.f) * sw2s[hf * 64 + i];
        s += __shfl_xor_sync(0xFFFFFFFFu, s, 1);
        if (hf == 0)
            Cf[zb * strCb + zh * strCh + m0 + row] = s + sb2g[0];
    } else {
        const float4* srow = (const float4*)(cs + row * 132 + hf * 64);
        const long cbase = zb * strCb + zh * strCh + (m0 + row) * (long)ldc + n0 + hf * 64;
        __half2* hrow = (__half2*)(Chi + cbase);
#pragma unroll
        for (int i = 0; i < 16; i++) {
            float4 v = srow[i];
            hrow[2 * i]     = __halves2half2(__float2half_rn(v.x), __float2half_rn(v.y));
            hrow[2 * i + 1] = __halves2half2(__float2half_rn(v.z), __float2half_rn(v.w));
        }
    }
}

// =================== WIDE 1-prod HMMA GEMM (128x256 tile, 256 thr) ==========
// EMIT 5: merged Q(+hi emit) / score-head tiles by blockIdx.x.
#define STGW (PLANE_B + PLANE_BW)

template<int EMIT>
__global__ __launch_bounds__(256, 1) void hgemm_w(
    const __half* __restrict__ Ahi, const __half* __restrict__ Bhi,
    float* __restrict__ Cf, __half* __restrict__ Chi,
    int lda, int ldb, int ldc, int Kd,
    const float* __restrict__ sb1g, const float* __restrict__ sw2g,
    const float* __restrict__ sb2g)
{
    extern __shared__ char smem[];
    const uint32_t smb = smem_u32(smem);
    const int tid  = threadIdx.x;
    const int wid  = tid >> 5;
    const int lane = tid & 31;
    const int wm   = wid & 1;
    const int wn   = wid >> 1;
    const int qrow = lane >> 2;
    const int qk   = (lane & 3) * 2;

    const long m0 = (long)blockIdx.y * 128;
    const long n0 = (long)blockIdx.x * 256;

    const __half* gA = Ahi + m0 * lda;
    const __half* gB = Bhi + n0 * ldb;

    const int r0 = tid >> 2, s0 = tid & 3;

    float acc[4][8][4];
#pragma unroll
    for (int i = 0; i < 4; i++)
#pragma unroll
        for (int j = 0; j < 8; j++)
#pragma unroll
            for (int r = 0; r < 4; r++) acc[i][j][r] = 0.f;

    const int NC = Kd / 32;

    cp16(smb + r0 * (SKW * 2) + s0 * 16, gA + (long)r0 * lda + s0 * 8);
    cp16(smb + (r0 + 64) * (SKW * 2) + s0 * 16, gA + (long)(r0 + 64) * lda + s0 * 8);
#pragma unroll
    for (int q = 0; q < 4; q++)
        cp16(smb + PLANE_B + (r0 + q * 64) * (SKW * 2) + s0 * 16,
             gB + (long)(r0 + q * 64) * ldb + s0 * 8);
    cp_commit();

    for (int ch = 0; ch < NC; ch++) {
        const int st = ch & 1;
        if (ch + 1 < NC) {
            const int k0 = (ch + 1) * 32;
            const uint32_t sb = smb + (st ^ 1) * STGW;
            cp16(sb + r0 * (SKW * 2) + s0 * 16, gA + (long)r0 * lda + k0 + s0 * 8);
            cp16(sb + (r0 + 64) * (SKW * 2) + s0 * 16, gA + (long)(r0 + 64) * lda + k0 + s0 * 8);
#pragma unroll
            for (int q = 0; q < 4; q++)
                cp16(sb + PLANE_B + (r0 + q * 64) * (SKW * 2) + s0 * 16,
                     gB + (long)(r0 + q * 64) * ldb + k0 + s0 * 8);
            cp_commit();
            cp_wait<1>();
        } else {
            cp_wait<0>();
        }
        __syncthreads();

        const uint32_t* pA = (const uint32_t*)(smem + st * STGW);
        const uint32_t* pB = (const uint32_t*)(smem + st * STGW + PLANE_B);

#pragma unroll
        for (int ks = 0; ks < 2; ks++) {
            const int kb = ks * 16;
            uint32_t af[4][4], bf[8][2];
#pragma unroll
            for (int mt = 0; mt < 4; mt++) {
                const int mr = wm * 64 + mt * 16 + qrow;
                af[mt][0] = pA[(mr * SKW + kb + qk) >> 1];
                af[mt][1] = pA[((mr + 8) * SKW + kb + qk) >> 1];
                af[mt][2] = pA[(mr * SKW + kb + qk + 8) >> 1];
                af[mt][3] = pA[((mr + 8) * SKW + kb + qk + 8) >> 1];
            }
#pragma unroll
            for (int nt = 0; nt < 8; nt++) {
                const int nr = wn * 64 + nt * 8 + qrow;
                bf[nt][0] = pB[(nr * SKW + kb + qk) >> 1];
                bf[nt][1] = pB[(nr * SKW + kb + qk + 8) >> 1];
            }
#pragma unroll
            for (int mt = 0; mt < 4; mt++)
#pragma unroll
                for (int nt = 0; nt < 8; nt++)
                    mma16816(acc[mt][nt], af[mt], bf[nt][0], bf[nt][1]);
        }
        __syncthreads();
    }

    float* cs = (float*)smem;   // [128][260]
    float* sb1s = (float*)(smem + 128 * 260 * 4);
    float* sw2s = sb1s + 128;
#pragma unroll
    for (int mt = 0; mt < 4; mt++) {
#pragma unroll
        for (int nt = 0; nt < 8; nt++) {
            const int r = wm * 64 + mt * 16 + qrow;
            const int c = wn * 64 + nt * 8 + (lane & 3) * 2;
            cs[r * 260 + c]           = acc[mt][nt][0];
            cs[r * 260 + c + 1]       = acc[mt][nt][1];
            cs[(r + 8) * 260 + c]     = acc[mt][nt][2];
            cs[(r + 8) * 260 + c + 1] = acc[mt][nt][3];
        }
    }
    if (EMIT == 5) {
        if (tid < 128) sb1s[tid] = sb1g[tid];
        else           sw2s[tid - 128] = sw2g[tid - 128];
    }
    __syncthreads();
    {
        const int row = tid >> 1;
        const int hf  = tid & 1;
        if (EMIT == 0) {
            const float4* srow = (const float4*)(cs + row * 260 + hf * 128);
            float4* crow = (float4*)(Cf + (m0 + row) * (long)ldc + n0 + hf * 128);
#pragma unroll
            for (int i = 0; i < 32; i++) crow[i] = srow[i];
        } else {  // EMIT == 5
            if ((int)blockIdx.x < 8) {
                const float4* srow = (const float4*)(cs + row * 260 + hf * 128);
                __half2* hrow = (__half2*)(Chi + (m0 + row) * (long)ldc + n0 + hf * 128);
#pragma unroll
                for (int i = 0; i < 32; i++) {
                    float4 v = srow[i];
                    hrow[2 * i]     = __halves2half2(__float2half_rn(v.x), __float2half_rn(v.y));
                    hrow[2 * i + 1] = __halves2half2(__float2half_rn(v.z), __float2half_rn(v.w));
                }
            } else {
                const float* crow = cs + row * 260 + hf * 128;
                float s = 0.f;
#pragma unroll
                for (int i = 0; i < 128; i++)
                    s += fmaxf(crow[i] + sb1s[i], 0.f) * sw2s[i];
                const long m = m0 + row;
                const int b = (int)(m >> 12);
                const int sq = (int)(m & 4095);
                const int h = ((int)blockIdx.x - 8) * 2 + hf;
                Cf[((long)(b * NHEADS + h)) * SS + sq] = s + sb2g[0];
            }
        }
    }
}

// =================== 64x256 1-prod HMMA GEMM (fp32 out), 256 thr ============
// For wo projection: grid (HH/256, NROWS/64) = 1024 tiles -> 6.92 waves.
#define STG64 (PLANE_A64 + PLANE_BW)   // 25600 per stage

__global__ __launch_bounds__(256, 1) void hgemm_w64(
    const __half* __restrict__ Ahi, const __half* __restrict__ Bhi,
    float* __restrict__ Cf, int lda, int ldb, int ldc, int Kd)
{
    extern __shared__ char smem[];
    const uint32_t smb = smem_u32(smem);
    const int tid  = threadIdx.x;
    const int wid  = tid >> 5;
    const int lane = tid & 31;
    const int wm   = wid & 1;        // 2 M groups of 32
    const int wn   = wid >> 1;       // 4 N groups of 64
    const int qrow = lane >> 2;
    const int qk   = (lane & 3) * 2;

    const long m0 = (long)blockIdx.y * 64;
    const long n0 = (long)blockIdx.x * 256;

    const __half* gA = Ahi + m0 * lda;
    const __half* gB = Bhi + n0 * ldb;

    const int r0 = tid >> 2, s0 = tid & 3;   // r0 in [0,64)

    float acc[2][8][4];
#pragma unroll
    for (int i = 0; i < 2; i++)
#pragma unroll
        for (int j = 0; j < 8; j++)
#pragma unroll
            for (int r = 0; r < 4; r++) acc[i][j][r] = 0.f;

    const int NC = Kd / 32;

    cp16(smb + r0 * (SKW * 2) + s0 * 16, gA + (long)r0 * lda + s0 * 8);
#pragma unroll
    for (int q = 0; q < 4; q++)
        cp16(smb + PLANE_A64 + (r0 + q * 64) * (SKW * 2) + s0 * 16,
             gB + (long)(r0 + q * 64) * ldb + s0 * 8);
    cp_commit();

    for (int ch = 0; ch < NC; ch++) {
        const int st = ch & 1;
        if (ch + 1 < NC) {
            const int k0 = (ch + 1) * 32;
            const uint32_t sb = smb + (st ^ 1) * STG64;
            cp16(sb + r0 * (SKW * 2) + s0 * 16, gA + (long)r0 * lda + k0 + s0 * 8);
#pragma unroll
            for (int q = 0; q < 4; q++)
                cp16(sb + PLANE_A64 + (r0 + q * 64) * (SKW * 2) + s0 * 16,
                     gB + (long)(r0 + q * 64) * ldb + k0 + s0 * 8);
            cp_commit();
            cp_wait<1>();
        } else {
            cp_wait<0>();
        }
        __syncthreads();

        const uint32_t* pA = (const uint32_t*)(smem + st * STG64);
        const uint32_t* pB = (const uint32_t*)(smem + st * STG64 + PLANE_A64);

#pragma unroll
        for (int ks = 0; ks < 2; ks++) {
            const int kb = ks * 16;
            uint32_t af[2][4], bf[8][2];
#pragma unroll
            for (int mt = 0; mt < 2; mt++) {
                const int mr = wm * 32 + mt * 16 + qrow;
                af[mt][0] = pA[(mr * SKW + kb + qk) >> 1];
                af[mt][1] = pA[((mr + 8) * SKW + kb + qk) >> 1];
                af[mt][2] = pA[(mr * SKW + kb + qk + 8) >> 1];
                af[mt][3] = pA[((mr + 8) * SKW + kb + qk + 8) >> 1];
            }
#pragma unroll
            for (int nt = 0; nt < 8; nt++) {
                const int nr = wn * 64 + nt * 8 + qrow;
                bf[nt][0] = pB[(nr * SKW + kb + qk) >> 1];
                bf[nt][1] = pB[(nr * SKW + kb + qk + 8) >> 1];
            }
#pragma unroll
            for (int mt = 0; mt < 2; mt++)
#pragma unroll
                for (int nt = 0; nt < 8; nt++)
                    mma16816(acc[mt][nt], af[mt], bf[nt][0], bf[nt][1]);
        }
        __syncthreads();
    }

    float* cs = (float*)smem;   // [64][260]
#pragma unroll
    for (int mt = 0; mt < 2; mt++) {
#pragma unroll
        for (int nt = 0; nt < 8; nt++) {
            const int r = wm * 32 + mt * 16 + qrow;
            const int c = wn * 64 + nt * 8 + (lane & 3) * 2;
            cs[r * 260 + c]           = acc[mt][nt][0];
            cs[r * 260 + c + 1]       = acc[mt][nt][1];
            cs[(r + 8) * 260 + c]     = acc[mt][nt][2];
            cs[(r + 8) * 260 + c + 1] = acc[mt][nt][3];
        }
    }
    __syncthreads();
    {
        const int row = tid >> 2;      // 64 rows, 4 threads/row
        const int q   = tid & 3;
        const float4* srow = (const float4*)(cs + row * 260 + q * 64);
        float4* crow = (float4*)(Cf + (m0 + row) * (long)ldc + n0 + q * 64);
#pragma unroll
        for (int i = 0; i < 16; i++) crow[i] = srow[i];
    }
}

// =================== fused attention (unchanged) ===================
#define FA_STR  136
#define FA_PLNB (128 * FA_STR * 2)

__global__ __launch_bounds__(256, 1) void fused_attn(
    const __half* __restrict__ Qg, const __half* __restrict__ Kg,
    const __half* __restrict__ Vg, __half* __restrict__ Og, float scale)
{
    extern __shared__ char smem[];
    __half* Qp = (__half*)smem;
    __half* Kp = (__half*)(smem + FA_PLNB);
    __half* Vp = (__half*)(smem + 2 * FA_PLNB);
    float*  red = (float*)(smem + 3 * FA_PLNB);
    const int tid  = threadIdx.x;
    const int wid  = tid >> 5;
    const int lane = tid & 31;
    const int wm   = wid & 1;
    const int wn   = wid >> 1;
    const int qrow = lane >> 2;
    const int qk   = (lane & 3) * 2;

    const int bh = blockIdx.y, zb = bh >> 4, zh = bh & 15;
    const long m0 = (long)blockIdx.x * 128;

    const __half* Qsrc = Qg + ((long)zb * SS + m0) * HH + zh * HDIM;
    const __half* Ksrc = Kg + (long)bh * (KSEL * HDIM);
    const __half* Vsrc = Vg + (long)bh * (KSEL * HDIM);

#pragma unroll
    for (int e = 0; e < 8; e++) {
        int idx = tid + e * 256;
        int r = idx >> 4, s = idx & 15;
        ((uint4*)Qp)[r * 17 + s] = ((const uint4*)(Qsrc + (long)r * HH))[s];
        ((uint4*)Kp)[r * 17 + s] = ((const uint4*)(Ksrc + r * HDIM))[s];
        ((uint4*)Vp)[r * 17 + s] = ((const uint4*)(Vsrc + r * HDIM))[s];
    }
    __syncthreads();

    float acc[4][4][4];
#pragma unroll
    for (int i = 0; i < 4; i++)
#pragma unroll
        for (int j = 0; j < 4; j++)
#pragma unroll
            for (int r = 0; r < 4; r++) acc[i][j][r] = 0.f;
    {
        const uint32_t* pQ = (const uint32_t*)Qp;
        const uint32_t* pK = (const uint32_t*)Kp;
#pragma unroll
        for (int kc = 0; kc < 8; kc++) {
            const int kb = kc * 16;
            uint32_t af[4][4], bf[4][2];
#pragma unroll
            for (int mt = 0; mt < 4; mt++) {
                const int mr = wm * 64 + mt * 16 + qrow;
                af[mt][0] = pQ[(mr * FA_STR + kb + qk) >> 1];
                af[mt][1] = pQ[((mr + 8) * FA_STR + kb + qk) >> 1];
                af[mt][2] = pQ[(mr * FA_STR + kb + qk + 8) >> 1];
                af[mt][3] = pQ[((mr + 8) * FA_STR + kb + qk + 8) >> 1];
            }
#pragma unroll
            for (int nt = 0; nt < 4; nt++) {
                const int nr = wn * 32 + nt * 8 + qrow;
                bf[nt][0] = pK[(nr * FA_STR + kb + qk) >> 1];
                bf[nt][1] = pK[(nr * FA_STR + kb + qk + 8) >> 1];
            }
#pragma unroll
            for (int mt = 0; mt < 4; mt++)
#pragma unroll
                for (int nt = 0; nt < 4; nt++)
                    mma16816(acc[mt][nt], af[mt], bf[nt][0], bf[nt][1]);
        }
    }

    float rmax[8];
#pragma unroll
    for (int mt = 0; mt < 4; mt++) {
        float m0v = -1e30f, m1v = -1e30f;
#pragma unroll
        for (int nt = 0; nt < 4; nt++) {
            m0v = fmaxf(m0v, fmaxf(acc[mt][nt][0], acc[mt][nt][1]));
            m1v = fmaxf(m1v, fmaxf(acc[mt][nt][2], acc[mt][nt][3]));
        }
        rmax[mt * 2]     = m0v;
        rmax[mt * 2 + 1] = m1v;
    }
#pragma unroll
    for (int i = 0; i < 8; i++) {
        rmax[i] = fmaxf(rmax[i], __shfl_xor_sync(0xFFFFFFFFu, rmax[i], 1));
        rmax[i] = fmaxf(rmax[i], __shfl_xor_sync(0xFFFFFFFFu, rmax[i], 2));
    }
    if ((lane & 3) == 0) {
#pragma unroll
        for (int mt = 0; mt < 4; mt++) {
            red[(wm * 64 + mt * 16 + qrow) * 4 + wn]     = rmax[mt * 2];
            red[(wm * 64 + mt * 16 + qrow + 8) * 4 + wn] = rmax[mt * 2 + 1];
        }
    }
    __syncthreads();
#pragma unroll
    for (int mt = 0; mt < 4; mt++) {
        const int r0r = wm * 64 + mt * 16 + qrow;
        float g0 = fmaxf(fmaxf(red[r0r * 4], red[r0r * 4 + 1]), fmaxf(red[r0r * 4 + 2], red[r0r * 4 + 3]));
        const int r1r = r0r + 8;
        float g1 = fmaxf(fmaxf(red[r1r * 4], red[r1r * 4 + 1]), fmaxf(red[r1r * 4 + 2], red[r1r * 4 + 3]));
        rmax[mt * 2] = g0; rmax[mt * 2 + 1] = g1;
    }
    __syncthreads();
    float rsum[8];
#pragma unroll
    for (int i = 0; i < 8; i++) rsum[i] = 0.f;
#pragma unroll
    for (int mt = 0; mt < 4; mt++)
#pragma unroll
        for (int nt = 0; nt < 4; nt++) {
            acc[mt][nt][0] = expf(acc[mt][nt][0] * scale - rmax[mt * 2] * scale);
            acc[mt][nt][1] = expf(acc[mt][nt][1] * scale - rmax[mt * 2] * scale);
            acc[mt][nt][2] = expf(acc[mt][nt][2] * scale - rmax[mt * 2 + 1] * scale);
            acc[mt][nt][3] = expf(acc[mt][nt][3] * scale - rmax[mt * 2 + 1] * scale);
            rsum[mt * 2]     += acc[mt][nt][0] + acc[mt][nt][1];
            rsum[mt * 2 + 1] += acc[mt][nt][2] + acc[mt][nt][3];
        }
#pragma unroll
    for (int i = 0; i < 8; i++) {
        rsum[i] += __shfl_xor_sync(0xFFFFFFFFu, rsum[i], 1);
        rsum[i] += __shfl_xor_sync(0xFFFFFFFFu, rsum[i], 2);
    }
    if ((lane & 3) == 0) {
#pragma unroll
        for (int mt = 0; mt < 4; mt++) {
            red[(wm * 64 + mt * 16 + qrow) * 4 + wn]     = rsum[mt * 2];
            red[(wm * 64 + mt * 16 + qrow + 8) * 4 + wn] = rsum[mt * 2 + 1];
        }
    }
    __syncthreads();
#pragma unroll
    for (int mt = 0; mt < 4; mt++) {
        const int r0r = wm * 64 + mt * 16 + qrow;
        rsum[mt * 2]     = 1.0f / (red[r0r * 4] + red[r0r * 4 + 1] + red[r0r * 4 + 2] + red[r0r * 4 + 3]);
        const int r1r = r0r + 8;
        rsum[mt * 2 + 1] = 1.0f / (red[r1r * 4] + red[r1r * 4 + 1] + red[r1r * 4 + 2] + red[r1r * 4 + 3]);
    }
    __syncthreads();

#pragma unroll
    for (int mt = 0; mt < 4; mt++)
#pragma unroll
        for (int nt = 0; nt < 4; nt++) {
            const int r = wm * 64 + mt * 16 + qrow;
            const int c = wn * 32 + nt * 8 + qk;
            *(__half2*)(Qp + r * FA_STR + c) =
                __halves2half2(__float2half_rn(acc[mt][nt][0] * rsum[mt * 2]),
                               __float2half_rn(acc[mt][nt][1] * rsum[mt * 2]));
            *(__half2*)(Qp + (r + 8) * FA_STR + c) =
                __halves2half2(__float2half_rn(acc[mt][nt][2] * rsum[mt * 2 + 1]),
                               __float2half_rn(acc[mt][nt][3] * rsum[mt * 2 + 1]));
        }
    __syncthreads();

#pragma unroll
    for (int i = 0; i < 4; i++)
#pragma unroll
        for (int j = 0; j < 4; j++)
#pragma unroll
            for (int r = 0; r < 4; r++) acc[i][j][r] = 0.f;
    {
        const uint32_t* pP = (const uint32_t*)Qp;
        const uint32_t* pV = (const uint32_t*)Vp;
#pragma unroll
        for (int kc = 0; kc < 8; kc++) {
            const int kb = kc * 16;
            uint32_t af[4][4], bf[4][2];
#pragma unroll
            for (int mt = 0; mt < 4; mt++) {
                const int mr = wm * 64 + mt * 16 + qrow;
                af[mt][0] = pP[(mr * FA_STR + kb + qk) >> 1];
                af[mt][1] = pP[((mr + 8) * FA_STR + kb + qk) >> 1];
                af[mt][2] = pP[(mr * FA_STR + kb + qk + 8) >> 1];
                af[mt][3] = pP[((mr + 8) * FA_STR + kb + qk + 8) >> 1];
            }
#pragma unroll
            for (int nt = 0; nt < 4; nt++) {
                const int nr = wn * 32 + nt * 8 + qrow;
                bf[nt][0] = pV[(nr * FA_STR + kb + qk) >> 1];
                bf[nt][1] = pV[(nr * FA_STR + kb + qk + 8) >> 1];
            }
#pragma unroll
            for (int mt = 0; mt < 4; mt++)
#pragma unroll
                for (int nt = 0; nt < 4; nt++)
                    mma16816(acc[mt][nt], af[mt], bf[nt][0], bf[nt][1]);
        }
    }

#pragma unroll
    for (int mt = 0; mt < 4; mt++)
#pragma unroll
        for (int nt = 0; nt < 4; nt++) {
            const int r = wm * 64 + mt * 16 + qrow;
            const int c = wn * 32 + nt * 8 + qk;
            __half* dst0 = Og + ((long)zb * SS + m0 + r) * HH + zh * HDIM + c;
            __half* dst1 = Og + ((long)zb * SS + m0 + r + 8) * HH + zh * HDIM + c;
            *(__half2*)dst0 = __halves2half2(__float2half_rn(acc[mt][nt][0]), __float2half_rn(acc[mt][nt][1]));
            *(__half2*)dst1 = __halves2half2(__float2half_rn(acc[mt][nt][2]), __float2half_rn(acc[mt][nt][3]));
        }
}

// ---------------- sparsek projection + approx top-k + band ----------------
__device__ __forceinline__ unsigned enc_desc(float v) {
    unsigned b = __float_as_uint(v);
    unsigned o = (b & 0x80000000u) ? ~b : (b | 0x80000000u);
    return ~o;
}
__device__ __forceinline__ float dec_desc(unsigned d) {
    unsigned o = ~d;
    unsigned b = (o & 0x80000000u) ? (o ^ 0x80000000u) : ~o;
    return __uint_as_float(b);
}

__global__ __launch_bounds__(1024) void sparsek_topk(const float* __restrict__ scores,
                                                     int* __restrict__ out_idx,
                                                     int* __restrict__ band,
                                                     int* __restrict__ nposg)
{
    __shared__ unsigned long long key[SS];
    __shared__ unsigned char flag[SS];
    __shared__ float fred[32];
    __shared__ int   ired[32];
    __shared__ int   rho_s, npos_s;
    __shared__ float tau_s;
    int bh  = blockIdx.x;
    int tid = threadIdx.x;
    int lane = tid & 31, warp = tid >> 5;
    const float* s = scores + (long)bh * SS;

    for (int i = tid; i < SS; i += 1024)
        key[i] = ((unsigned long long)enc_desc(s[i]) << 32) | (unsigned)i;
    __syncthreads();

    for (int k = 2; k <= SS; k <<= 1) {
        for (int j = k >> 1; j > 0; j >>= 1) {
            for (int i = tid; i < SS; i += 1024) {
                int ixj = i ^ j;
                if (ixj > i) {
                    bool up = ((i & k) == 0);
                    unsigned long long a = key[i], b = key[ixj];
                    if ((a > b) == up) { key[i] = b; key[ixj] = a; }
                }
            }
            __syncthreads();
        }
    }

    if (tid < BAND)
        band[bh * BAND + tid] = (int)(key[tid] & 0xFFFFFFFFu);

    float v[4], pc[4];
#pragma unroll
    for (int j = 0; j < 4; j++) v[j] = dec_desc((unsigned)(key[tid * 4 + j] >> 32));
    pc[0] = v[0]; pc[1] = pc[0] + v[1]; pc[2] = pc[1] + v[2]; pc[3] = pc[2] + v[3];
    float tot = pc[3];
#pragma unroll
    for (int o = 1; o < 32; o <<= 1) {
        float n = __shfl_up_sync(0xFFFFFFFFu, tot, o);
        if (lane >= o) tot += n;
    }
    if (lane == 31) fred[warp] = tot;
    __syncthreads();
    if (warp == 0) {
        float w = fred[lane];
#pragma unroll
        for (int o = 1; o < 32; o <<= 1) {
            float n = __shfl_up_sync(0xFFFFFFFFu, w, o);
            if (lane >= o) w += n;
        }
        fred[lane] = w;
    }
    __syncthreads();
    const float base = (warp ? fred[warp - 1] : 0.f) + (tot - pc[3]);

    int cnt = 0;
#pragma unroll
    for (int j = 0; j < 4; j++) {
        float csj = base + pc[j];
        float thr = (csj - (float)KSEL) / (float)(tid * 4 + j + 1);
        if (v[j] > thr) cnt++;
    }
#pragma unroll
    for (int o = 16; o > 0; o >>= 1) cnt += __shfl_xor_sync(0xFFFFFFFFu, cnt, o);
    if (lane == 0) ired[warp] = cnt;
    __syncthreads();
    if (tid == 0) {
        int r = 0;
#pragma unroll
        for (int i = 0; i < 32; i++) r += ired[i];
        rho_s = (r < 1) ? 1 : r;
    }
    __syncthreads();
    const int rho = rho_s;
    {
        int rr = rho - 1;
        if ((rr >> 2) == tid)
            tau_s = (base + pc[rr & 3] - (float)KSEL) / (float)rho;
    }
    __syncthreads();
    const float tau = tau_s;
    int cnp = 0;
#pragma unroll
    for (int j = 0; j < 4; j++) if (v[j] > tau) cnp++;
#pragma unroll
    for (int o = 16; o > 0; o >>= 1) cnp += __shfl_xor_sync(0xFFFFFFFFu, cnp, o);
    if (lane == 0) ired[warp] = cnp;
    __syncthreads();
    if (tid == 0) {
        int r = 0;
#pragma unroll
        for (int i = 0; i < 32; i++) r += ired[i];
        npos_s = r;
        nposg[bh] = r;
    }
    __syncthreads();

    const int npos = npos_s;
    if (npos >= KSEL) {
        if (tid < KSEL)
            out_idx[bh * KSEL + tid] = (int)(key[tid] & 0xFFFFFFFFu);
    } else {
        if (tid < npos)
            out_idx[bh * KSEL + tid] = (int)(key[tid] & 0xFFFFFFFFu);
        for (int i = tid; i < SS; i += 1024) flag[i] = 0;
        __syncthreads();
        for (int i = tid; i < npos; i += 1024)
            flag[key[i] & 0xFFFFFFFFu] = 1;
        __syncthreads();
        if (tid == 0) {
            int c2 = npos;
            for (int i = 0; i < SS && c2 < KSEL; i++)
                if (!flag[i]) out_idx[bh * KSEL + c2++] = i;
        }
    }
}

// ---------------- merge: exact top-128 from rescored band ----------------
__global__ __launch_bounds__(256) void merge_band(const float* __restrict__ sc,
                                                  const int* __restrict__ band,
                                                  const int* __restrict__ nposg,
                                                  int* __restrict__ out_idx)
{
    __shared__ unsigned long long key[BAND];
    int bh = blockIdx.x, t = threadIdx.x;
    key[t] = ((unsigned long long)enc_desc(sc[bh * BAND + t]) << 32)
           | (unsigned)band[bh * BAND + t];
    __syncthreads();
    for (int k = 2; k <= BAND; k <<= 1) {
        for (int j = k >> 1; j > 0; j >>= 1) {
            int ixj = t ^ j;
            if (ixj > t) {
                bool up = ((t & k) == 0);
                unsigned long long a = key[t], b = key[ixj];
                if ((a > b) == up) { key[t] = b; key[ixj] = a; }
            }
            __syncthreads();
        }
    }
    if (nposg[bh] >= KSEL && t < KSEL)
        out_idx[bh * KSEL + t] = (int)(key[t] & 0xFFFFFFFFu);
}

// ---------------- launch ----------------
extern "C" void kernel_launch(void* const* d_in, const int* in_sizes, int n_in,
                              void* d_out, int out_size)
{
    const float* x   = (const float*)d_in[0];
    const float* wq  = (const float*)d_in[1];
    const float* wk  = (const float*)d_in[2];
    const float* wv  = (const float*)d_in[3];
    const float* wo  = (const float*)d_in[4];
    const float* sw1 = (const float*)d_in[5];
    const float* sb1 = (const float*)d_in[6];
    const float* sw2 = (const float*)d_in[7];
    const float* sb2 = (const float*)d_in[8];
    float* out = (float*)d_out;

    float *pScores, *pS256;
    int *pIdx, *pBand, *pNpos;
    __half *pXhi, *pXlo, *pQhi, *pOhi;
    __half *pWBig, *pWk, *pWv, *pWo, *pWchi, *pWclo, *pKselh, *pVselTh;
    cudaGetSymbolAddress((void**)&pScores, gScores);
    cudaGetSymbolAddress((void**)&pS256,   gS256);
    cudaGetSymbolAddress((void**)&pIdx,    gIdx);
    cudaGetSymbolAddress((void**)&pBand,   gBand);
    cudaGetSymbolAddress((void**)&pNpos,   gNpos);
    cudaGetSymbolAddress((void**)&pXhi,    gXhi);
    cudaGetSymbolAddress((void**)&pXlo,    gXlo);
    cudaGetSymbolAddress((void**)&pQhi,    gQhi);
    cudaGetSymbolAddress((void**)&pOhi,    gOhi);
    cudaGetSymbolAddress((void**)&pWBig,   gWBig);
    cudaGetSymbolAddress((void**)&pWk,     gWk);
    cudaGetSymbolAddress((void**)&pWv,     gWv);
    cudaGetSymbolAddress((void**)&pWo,     gWo);
    cudaGetSymbolAddress((void**)&pWchi,   gWchi);
    cudaGetSymbolAddress((void**)&pWclo,   gWclo);
    cudaGetSymbolAddress((void**)&pKselh,  gKselh);
    cudaGetSymbolAddress((void**)&pVselTh, gVselTh);

    const int SM12 = 67584;
    const int SM33 = 81920;
    const int SMW  = 128 * 260 * 4 + 1024;   // 134144
    const int SM64 = 66560;                  // max(2*25600, 64*260*4)
    const int SMA  = 3 * FA_PLNB + 128 * 4 * 4;
    cudaFuncSetAttribute(hgemm_w<5>, cudaFuncAttributeMaxDynamicSharedMemorySize, SMW);
    cudaFuncSetAttribute(hgemm_w64, cudaFuncAttributeMaxDynamicSharedMemorySize, SM64);
    cudaFuncSetAttribute(hgemm<1,2,1>, cudaFuncAttributeMaxDynamicSharedMemorySize, SM12);
    cudaFuncSetAttribute(hgemm<1,2,2>, cudaFuncAttributeMaxDynamicSharedMemorySize, SM12);
    cudaFuncSetAttribute(hgemm<3,3,1>, cudaFuncAttributeMaxDynamicSharedMemorySize, SM33);
    cudaFuncSetAttribute(fused_attn, cudaFuncAttributeMaxDynamicSharedMemorySize, SMA);

    const long sSelh = (long)KSEL * HDIM;
    const long sWh   = (long)HDIM * HH;

    dim3 gMerged(2 * HH / 256, NROWS / 128, 1);  // (16, 64)
    dim3 gWo(HH / 256, NROWS / 64, 1);           // (8, 128) = 1024 tiles
    dim3 gResc(1, BAND / 128, NBH);              // (1, 2, 32)
    dim3 gSel(1, 1, NBH);                        // (1, 1, 32)
    dim3 gFA(SS / 128, NBH);                     // (32, 32)

    // ---- splits + composed score weight ----
    splitX<<<(int)((ROWHID / 8 + 255) / 256), 256>>>(x, pXhi, pXlo, ROWHID / 8);
    splitW<<<(int)((WN / 8 + 255) / 256), 256>>>(wq, wk, wv, wo, pWBig, pWk, pWv, pWo);
    wc_make<<<16 * 64, 256>>>(sw1, wk, pWchi, pWclo, pWBig);

    // ---- merged: Q = X@wq^T  +  approx scores = head(X@Wc^T) ----
    hgemm_w<5><<<gMerged, 256, SMW>>>(pXhi, pWBig, pScores, pQhi, HH, HH, HH, HH,
                                      sb1, sw2, sb2);

    // ---- sort + sparsek stats + candidate band ----
    sparsek_topk<<<NBH, 1024>>>(pScores, pIdx, pBand, pNpos);

    // ---- rescore band exactly (3-prod composed, A rows indexed into X) ----
    hgemm<3,3,1><<<gResc, 256, SM33>>>(pXhi, pXlo, pWchi, pWclo, pS256, nullptr,
                                       HH, HH, 1,
                                       0, 0, 0, sWh, (long)NHEADS * BAND, (long)BAND,
                                       HH, 1.0f, sb1, sw2, sb2,
                                       pBand, BAND);
    merge_band<<<NBH, 256>>>(pS256, pBand, pNpos, pIdx);

    // ---- Ksel = Xsel @ wk_head^T (A indexed), VselT = wv_head @ Xsel^T (B indexed) ----
    hgemm<1,2,1><<<gSel, 256, SM12>>>(pXhi, nullptr, pWk, nullptr, nullptr, pKselh,
                                      HH, HH, HDIM,
                                      0, 0, 0, sWh,
                                      (long)NHEADS * KSEL * HDIM, sSelh,
                                      HH, 1.0f, nullptr, nullptr, nullptr,
                                      pIdx, KSEL);
    hgemm<1,2,2><<<gSel, 256, SM12>>>(pWv, nullptr, pXhi, nullptr, nullptr, pVselTh,
                                      HH, HH, KSEL,
                                      0, sWh, 0, 0,
                                      (long)NHEADS * KSEL * HDIM, sSelh,
                                      HH, 1.0f, nullptr, nullptr, nullptr,
                                      pIdx, KSEL);

    // ---- fused attention ----
    const float scale = 0.08838834764831845f;
    fused_attn<<<gFA, 256, SMA>>>(pQhi, pKselh, pVselTh, pOhi, scale);

    // ---- out = O @ wo^T (1-prod, 64x256 tiles, fp32 out) ----
    hgemm_w64<<<gWo, 256, SM64>>>(pOhi, pWo, out, HH, HH, HH, HH);
}

// round 17
// speedup vs baseline: 1.0326x; 1.0326x over previous
#include <cuda_runtime.h>
#include <cuda_fp16.h>
#include <math.h>
#include <stdint.h>

// ---------------- problem constants ----------------
#define BB        2
#define SS        4096
#define HH        2048
#define NHEADS    16
#define HDIM      128
#define KSEL      128
#define BAND      256
#define NROWS     (BB*SS)            // 8192
#define NBH       (BB*NHEADS)        // 32
#define ROWHID    ((long)NROWS*HH)   // 16777216
#define WN        ((long)HH*HH)      // 4194304
#define SELN      (NBH*KSEL*HDIM)    // 524288

// ---------------- scratch (device globals; no allocs allowed) ----------------
__device__ float  gScores[NBH*SS];
__device__ float  gS256[NBH*BAND];
__device__ int    gIdx[NBH*KSEL];
__device__ int    gBand[NBH*BAND];
__device__ int    gNpos[NBH];
__device__ __half gXhi[ROWHID];
__device__ __half gXlo[ROWHID];
__device__ __half gQhi[ROWHID];
__device__ __half gOhi[ROWHID];
__device__ __half gWBig[2*WN];       // rows 0..2047: wq_hi ; rows 2048..4095: Wc_hi
__device__ __half gWk[WN];
__device__ __half gWv[WN];
__device__ __half gWo[WN];
__device__ __half gWchi[WN];
__device__ __half gWclo[WN];
__device__ __half gKselh[SELN];
__device__ __half gVselTh[SELN];

// =================== helpers ===================
__device__ __forceinline__ uint32_t smem_u32(const void* p) {
    uint32_t a;
    asm("{ .reg .u64 t; cvta.to.shared.u64 t, %1; cvt.u32.u64 %0, t; }" : "=r"(a) : "l"(p));
    return a;
}
__device__ __forceinline__ void cp16(uint32_t dst, const void* src) {
    asm volatile("cp.async.cg.shared.global [%0], [%1], 16;" :: "r"(dst), "l"(src));
}
__device__ __forceinline__ void cp_commit() {
    asm volatile("cp.async.commit_group;" ::: "memory");
}
template<int N>
__device__ __forceinline__ void cp_wait() {
    asm volatile("cp.async.wait_group %0;" :: "n"(N) : "memory");
}
__device__ __forceinline__ void mma16816(float* c, const uint32_t* a, uint32_t b0, uint32_t b1) {
    asm volatile(
        "mma.sync.aligned.m16n8k16.row.col.f32.f16.f16.f32 "
        "{%0,%1,%2,%3}, {%4,%5,%6,%7}, {%8,%9}, {%0,%1,%2,%3};"
        : "+f"(c[0]), "+f"(c[1]), "+f"(c[2]), "+f"(c[3])
        : "r"(a[0]), "r"(a[1]), "r"(a[2]), "r"(a[3]), "r"(b0), "r"(b1));
}

// =================== vectorized splits (8 elems / thread) ===================
__device__ __forceinline__ void cvt1x8(const float* __restrict__ s, __half* __restrict__ d, long g) {
    const float4* sp = (const float4*)s + g * 2;
    float4 a = sp[0], b = sp[1];
    __half2 h0 = __halves2half2(__float2half_rn(a.x), __float2half_rn(a.y));
    __half2 h1 = __halves2half2(__float2half_rn(a.z), __float2half_rn(a.w));
    __half2 h2 = __halves2half2(__float2half_rn(b.x), __float2half_rn(b.y));
    __half2 h3 = __halves2half2(__float2half_rn(b.z), __float2half_rn(b.w));
    uint4 o;
    o.x = *(uint32_t*)&h0; o.y = *(uint32_t*)&h1;
    o.z = *(uint32_t*)&h2; o.w = *(uint32_t*)&h3;
    ((uint4*)d)[g] = o;
}
__device__ __forceinline__ void cvt2x8(const float* __restrict__ s,
                                       __half* __restrict__ dh, __half* __restrict__ dl, long g) {
    const float4* sp = (const float4*)s + g * 2;
    float4 a = sp[0], b = sp[1];
    float f[8] = {a.x, a.y, a.z, a.w, b.x, b.y, b.z, b.w};
    uint32_t hw[4], lw[4];
#pragma unroll
    for (int j = 0; j < 4; j++) {
        __half h0 = __float2half_rn(f[2 * j]);
        __half h1 = __float2half_rn(f[2 * j + 1]);
        __half l0 = __float2half_rn((f[2 * j] - __half2float(h0)) * 64.0f);
        __half l1 = __float2half_rn((f[2 * j + 1] - __half2float(h1)) * 64.0f);
        __half2 hh = __halves2half2(h0, h1);
        __half2 ll = __halves2half2(l0, l1);
        hw[j] = *(uint32_t*)&hh;
        lw[j] = *(uint32_t*)&ll;
    }
    ((uint4*)dh)[g] = make_uint4(hw[0], hw[1], hw[2], hw[3]);
    ((uint4*)dl)[g] = make_uint4(lw[0], lw[1], lw[2], lw[3]);
}

__global__ void splitX(const float* __restrict__ s, __half* __restrict__ hi,
                       __half* __restrict__ lo, long n8)
{
    long i = (long)blockIdx.x * blockDim.x + threadIdx.x;
    if (i >= n8) return;
    cvt2x8(s, hi, lo, i);
}

__global__ void splitW(const float* __restrict__ wq, const float* __restrict__ wk,
                       const float* __restrict__ wv, const float* __restrict__ wo,
                       __half* __restrict__ qbig, __half* __restrict__ k,
                       __half* __restrict__ v, __half* __restrict__ o)
{
    long i = (long)blockIdx.x * blockDim.x + threadIdx.x;
    if (i >= WN / 8) return;
    cvt1x8(wq, qbig, i);
    cvt1x8(wk, k, i);
    cvt1x8(wv, v, i);
    cvt1x8(wo, o, i);
}

// =================== Wc = sw1 @ wk_head (composed score weight) =============
__global__ __launch_bounds__(256) void wc_make(const float* __restrict__ sw1,
                                               const float* __restrict__ wk,
                                               __half* __restrict__ wchi,
                                               __half* __restrict__ wclo,
                                               __half* __restrict__ wbig)
{
    __shared__ float wks[128][33];
    const int h  = blockIdx.x >> 6;
    const int cb = (blockIdx.x & 63) * 32;
    const int t  = threadIdx.x;
#pragma unroll
    for (int e = 0; e < 16; e++) {
        int idx = t + e * 256;
        int k = idx >> 5, c = idx & 31;
        wks[k][c] = wk[(long)(h * 128 + k) * HH + cb + c];
    }
    __syncthreads();
    const int ip = t >> 1;
    const int cs = (t & 1) * 16;
    const float* s1r = sw1 + ip * HDIM;
    float acc[16];
#pragma unroll
    for (int j = 0; j < 16; j++) acc[j] = 0.f;
    for (int k = 0; k < 128; k++) {
        float s = s1r[k];
#pragma unroll
        for (int j = 0; j < 16; j++) acc[j] += s * wks[k][cs + j];
    }
    long base  = (long)(h * 128 + ip) * HH + cb + cs;
    long baseb = (long)(HH + h * 128 + ip) * HH + cb + cs;
#pragma unroll
    for (int j = 0; j < 16; j++) {
        __half hh = __float2half_rn(acc[j]);
        wchi[base + j] = hh;
        wbig[baseb + j] = hh;
        wclo[base + j] = __float2half_rn((acc[j] - __half2float(hh)) * 64.0f);
    }
}

#define SKW 40
#define PLANE_B (128 * SKW * 2)      // 10240 bytes
#define PLANE_BW (256 * SKW * 2)     // 20480 bytes

// =================== HMMA split GEMM (128x128 tile, 256 thr) ================
// NPROD 3/1. EMIT: 2 fp16 hi; 3 fused score head.
// IDX: 0 = none; 1 = A rows indexed into X; 2 = B rows indexed into X.
template<int NPROD, int EMIT, int IDX>
__global__ __launch_bounds__(256, 1) void hgemm(
    const __half* __restrict__ Ahi, const __half* __restrict__ Alo,
    const __half* __restrict__ Bhi, const __half* __restrict__ Blo,
    float* __restrict__ Cf, __half* __restrict__ Chi,
    int lda, int ldb, int ldc,
    long strAb, long strAh, long strBb, long strBh, long strCb, long strCh,
    int Kd, float alpha,
    const float* __restrict__ sb1g, const float* __restrict__ sw2g,
    const float* __restrict__ sb2g,
    const int* __restrict__ idxp, int idxN)
{
    constexpr int NPL = (NPROD == 3) ? 4 : (NPROD == 2 ? 3 : 2);
    constexpr int STG = NPL * PLANE_B;
    extern __shared__ char smem[];
    const uint32_t smb = smem_u32(smem);
    const int tid  = threadIdx.x;
    const int wid  = tid >> 5;
    const int lane = tid & 31;
    const int wm   = wid & 1;
    const int wn   = wid >> 1;
    const int qrow = lane >> 2;
    const int qk   = (lane & 3) * 2;

    const int z = blockIdx.z, zb = z >> 4, zh = z & 15;
    const long m0 = (long)blockIdx.y * 128;
    const long n0 = (long)blockIdx.x * 128;

    const __half* pg[4];
    int pld[4];
    pg[0] = Ahi + zb * strAb + zh * strAh + m0 * lda;  pld[0] = lda;
    pg[1] = Bhi + zb * strBb + zh * strBh + n0 * ldb;  pld[1] = ldb;
    pg[2] = (NPROD >= 2) ? (Blo + zb * strBb + zh * strBh + n0 * ldb) : pg[1];
    pld[2] = ldb;
    pg[3] = (NPROD == 3) ? (Alo + zb * strAb + zh * strAh + m0 * lda) : pg[0];
    pld[3] = lda;

    const int r0 = tid >> 2, s0 = tid & 3;
    const int r1 = r0 + 64;

    const __half* rp[4][2];
#pragma unroll
    for (int p = 0; p < NPL; p++) {
        const bool isA = (p == 0 || p == 3);
#pragma unroll
        for (int ri = 0; ri < 2; ri++) {
            const int r = (ri == 0) ? r0 : r1;
            if (IDX == 1 && isA) {
                int grow = idxp[(long)z * idxN + m0 + r];
                const __half* base = (p == 0) ? Ahi : Alo;
                rp[p][ri] = base + ((long)zb * SS + grow) * lda;
            } else if (IDX == 2 && !isA) {
                int grow = idxp[(long)z * idxN + n0 + r];
                const __half* base = (p == 1) ? Bhi : Blo;
                rp[p][ri] = base + ((long)zb * SS + grow) * ldb;
            } else {
                rp[p][ri] = pg[p] + (long)r * pld[p];
            }
        }
    }

    float acc[4][4][4], axx[4][4][4];
#pragma unroll
    for (int i = 0; i < 4; i++)
#pragma unroll
        for (int j = 0; j < 4; j++)
#pragma unroll
            for (int r = 0; r < 4; r++) { acc[i][j][r] = 0.f; axx[i][j][r] = 0.f; }

    const int NC = Kd / 32;

#pragma unroll
    for (int p = 0; p < NPL; p++) {
        cp16(smb + p * PLANE_B + r0 * (SKW * 2) + s0 * 16, rp[p][0] + s0 * 8);
        cp16(smb + p * PLANE_B + r1 * (SKW * 2) + s0 * 16, rp[p][1] + s0 * 8);
    }
    cp_commit();

    for (int ch = 0; ch < NC; ch++) {
        const int st = ch & 1;
        if (ch + 1 < NC) {
            const int k0 = (ch + 1) * 32;
            const uint32_t sb = smb + (st ^ 1) * STG;
#pragma unroll
            for (int p = 0; p < NPL; p++) {
                cp16(sb + p * PLANE_B + r0 * (SKW * 2) + s0 * 16, rp[p][0] + k0 + s0 * 8);
                cp16(sb + p * PLANE_B + r1 * (SKW * 2) + s0 * 16, rp[p][1] + k0 + s0 * 8);
            }
            cp_commit();
            cp_wait<1>();
        } else {
            cp_wait<0>();
        }
        __syncthreads();

        const uint32_t* pAh = (const uint32_t*)(smem + st * STG + 0 * PLANE_B);
        const uint32_t* pBh = (const uint32_t*)(smem + st * STG + 1 * PLANE_B);
        const uint32_t* pBl = (const uint32_t*)(smem + st * STG + 2 * PLANE_B);
        const uint32_t* pAl = (const uint32_t*)(smem + st * STG + 3 * PLANE_B);

#pragma unroll
        for (int ks = 0; ks < 2; ks++) {
            const int kb = ks * 16;
            uint32_t af[4][4], bf[4][2];
#pragma unroll
            for (int mt = 0; mt < 4; mt++) {
                const int mr = wm * 64 + mt * 16 + qrow;
                af[mt][0] = pAh[(mr * SKW + kb + qk) >> 1];
                af[mt][1] = pAh[((mr + 8) * SKW + kb + qk) >> 1];
                af[mt][2] = pAh[(mr * SKW + kb + qk + 8) >> 1];
                af[mt][3] = pAh[((mr + 8) * SKW + kb + qk + 8) >> 1];
            }
#pragma unroll
            for (int nt = 0; nt < 4; nt++) {
                const int nr = wn * 32 + nt * 8 + qrow;
                bf[nt][0] = pBh[(nr * SKW + kb + qk) >> 1];
                bf[nt][1] = pBh[(nr * SKW + kb + qk + 8) >> 1];
            }
#pragma unroll
            for (int mt = 0; mt < 4; mt++)
#pragma unroll
                for (int nt = 0; nt < 4; nt++)
                    mma16816(acc[mt][nt], af[mt], bf[nt][0], bf[nt][1]);
            if (NPROD >= 2) {
                uint32_t bl[4][2];
#pragma unroll
                for (int nt = 0; nt < 4; nt++) {
                    const int nr = wn * 32 + nt * 8 + qrow;
                    bl[nt][0] = pBl[(nr * SKW + kb + qk) >> 1];
                    bl[nt][1] = pBl[(nr * SKW + kb + qk + 8) >> 1];
                }
#pragma unroll
                for (int mt = 0; mt < 4; mt++)
#pragma unroll
                    for (int nt = 0; nt < 4; nt++)
                        mma16816(axx[mt][nt], af[mt], bl[nt][0], bl[nt][1]);
            }
            if (NPROD == 3) {
#pragma unroll
                for (int mt = 0; mt < 4; mt++) {
                    const int mr = wm * 64 + mt * 16 + qrow;
                    af[mt][0] = pAl[(mr * SKW + kb + qk) >> 1];
                    af[mt][1] = pAl[((mr + 8) * SKW + kb + qk) >> 1];
                    af[mt][2] = pAl[(mr * SKW + kb + qk + 8) >> 1];
                    af[mt][3] = pAl[((mr + 8) * SKW + kb + qk + 8) >> 1];
                }
#pragma unroll
                for (int mt = 0; mt < 4; mt++)
#pragma unroll
                    for (int nt = 0; nt < 4; nt++)
                        mma16816(axx[mt][nt], af[mt], bf[nt][0], bf[nt][1]);
            }
        }
        __syncthreads();
    }

    float* cs = (float*)smem;   // [128][132]
    float* sb1s = (float*)(smem + 128 * 132 * 4);
    float* sw2s = sb1s + 128;
    const float inv64 = 1.0f / 64.0f;
#pragma unroll
    for (int mt = 0; mt < 4; mt++) {
#pragma unroll
        for (int nt = 0; nt < 4; nt++) {
            const int r = wm * 64 + mt * 16 + qrow;
            const int c = wn * 32 + nt * 8 + (lane & 3) * 2;
            if (NPROD >= 2) {
                cs[r * 132 + c]           = alpha * (acc[mt][nt][0] + axx[mt][nt][0] * inv64);
                cs[r * 132 + c + 1]       = alpha * (acc[mt][nt][1] + axx[mt][nt][1] * inv64);
                cs[(r + 8) * 132 + c]     = alpha * (acc[mt][nt][2] + axx[mt][nt][2] * inv64);
                cs[(r + 8) * 132 + c + 1] = alpha * (acc[mt][nt][3] + axx[mt][nt][3] * inv64);
            } else {
                cs[r * 132 + c]           = alpha * acc[mt][nt][0];
                cs[r * 132 + c + 1]       = alpha * acc[mt][nt][1];
                cs[(r + 8) * 132 + c]     = alpha * acc[mt][nt][2];
                cs[(r + 8) * 132 + c + 1] = alpha * acc[mt][nt][3];
            }
        }
    }
    if (EMIT == 3) {
        if (tid < 128) sb1s[tid] = sb1g[tid];
        else           sw2s[tid - 128] = sw2g[tid - 128];
    }
    __syncthreads();

    const int row = tid >> 1;
    const int hf  = tid & 1;
    if (EMIT == 3) {
        const float* crow = cs + row * 132 + hf * 64;
        float s = 0.f;
#pragma unroll
        for (int i = 0; i < 64; i++)
            s += fmaxf(crow[i] + sb1s[hf * 64 + i], 0.f) * sw2s[hf * 64 + i];
        s += __shfl_xor_sync(0xFFFFFFFFu, s, 1);
        if (hf == 0)
            Cf[zb * strCb + zh * strCh + m0 + row] = s + sb2g[0];
    } else {
        const float4* srow = (const float4*)(cs + row * 132 + hf * 64);
        const long cbase = zb * strCb + zh * strCh + (m0 + row) * (long)ldc + n0 + hf * 64;
        __half2* hrow = (__half2*)(Chi + cbase);
#pragma unroll
        for (int i = 0; i < 16; i++) {
            float4 v = srow[i];
            hrow[2 * i]     = __halves2half2(__float2half_rn(v.x), __float2half_rn(v.y));
            hrow[2 * i + 1] = __halves2half2(__float2half_rn(v.z), __float2half_rn(v.w));
        }
    }
}

// =================== WIDE 1-prod HMMA GEMM (128x256 tile, 256 thr) ==========
// EMIT 0: fp32 out. EMIT 5: merged Q(+hi emit) / score-head tiles by blockIdx.x.
#define STGW (PLANE_B + PLANE_BW)

template<int EMIT>
__global__ __launch_bounds__(256, 1) void hgemm_w(
    const __half* __restrict__ Ahi, const __half* __restrict__ Bhi,
    float* __restrict__ Cf, __half* __restrict__ Chi,
    int lda, int ldb, int ldc, int Kd,
    const float* __restrict__ sb1g, const float* __restrict__ sw2g,
    const float* __restrict__ sb2g)
{
    extern __shared__ char smem[];
    const uint32_t smb = smem_u32(smem);
    const int tid  = threadIdx.x;
    const int wid  = tid >> 5;
    const int lane = tid & 31;
    const int wm   = wid & 1;
    const int wn   = wid >> 1;
    const int qrow = lane >> 2;
    const int qk   = (lane & 3) * 2;

    const long m0 = (long)blockIdx.y * 128;
    const long n0 = (long)blockIdx.x * 256;

    const __half* gA = Ahi + m0 * lda;
    const __half* gB = Bhi + n0 * ldb;

    const int r0 = tid >> 2, s0 = tid & 3;

    float acc[4][8][4];
#pragma unroll
    for (int i = 0; i < 4; i++)
#pragma unroll
        for (int j = 0; j < 8; j++)
#pragma unroll
            for (int r = 0; r < 4; r++) acc[i][j][r] = 0.f;

    const int NC = Kd / 32;

    cp16(smb + r0 * (SKW * 2) + s0 * 16, gA + (long)r0 * lda + s0 * 8);
    cp16(smb + (r0 + 64) * (SKW * 2) + s0 * 16, gA + (long)(r0 + 64) * lda + s0 * 8);
#pragma unroll
    for (int q = 0; q < 4; q++)
        cp16(smb + PLANE_B + (r0 + q * 64) * (SKW * 2) + s0 * 16,
             gB + (long)(r0 + q * 64) * ldb + s0 * 8);
    cp_commit();

    for (int ch = 0; ch < NC; ch++) {
        const int st = ch & 1;
        if (ch + 1 < NC) {
            const int k0 = (ch + 1) * 32;
            const uint32_t sb = smb + (st ^ 1) * STGW;
            cp16(sb + r0 * (SKW * 2) + s0 * 16, gA + (long)r0 * lda + k0 + s0 * 8);
            cp16(sb + (r0 + 64) * (SKW * 2) + s0 * 16, gA + (long)(r0 + 64) * lda + k0 + s0 * 8);
#pragma unroll
            for (int q = 0; q < 4; q++)
                cp16(sb + PLANE_B + (r0 + q * 64) * (SKW * 2) + s0 * 16,
                     gB + (long)(r0 + q * 64) * ldb + k0 + s0 * 8);
            cp_commit();
            cp_wait<1>();
        } else {
            cp_wait<0>();
        }
        __syncthreads();

        const uint32_t* pA = (const uint32_t*)(smem + st * STGW);
        const uint32_t* pB = (const uint32_t*)(smem + st * STGW + PLANE_B);

#pragma unroll
        for (int ks = 0; ks < 2; ks++) {
            const int kb = ks * 16;
            uint32_t af[4][4], bf[8][2];
#pragma unroll
            for (int mt = 0; mt < 4; mt++) {
                const int mr = wm * 64 + mt * 16 + qrow;
                af[mt][0] = pA[(mr * SKW + kb + qk) >> 1];
                af[mt][1] = pA[((mr + 8) * SKW + kb + qk) >> 1];
                af[mt][2] = pA[(mr * SKW + kb + qk + 8) >> 1];
                af[mt][3] = pA[((mr + 8) * SKW + kb + qk + 8) >> 1];
            }
#pragma unroll
            for (int nt = 0; nt < 8; nt++) {
                const int nr = wn * 64 + nt * 8 + qrow;
                bf[nt][0] = pB[(nr * SKW + kb + qk) >> 1];
                bf[nt][1] = pB[(nr * SKW + kb + qk + 8) >> 1];
            }
#pragma unroll
            for (int mt = 0; mt < 4; mt++)
#pragma unroll
                for (int nt = 0; nt < 8; nt++)
                    mma16816(acc[mt][nt], af[mt], bf[nt][0], bf[nt][1]);
        }
        __syncthreads();
    }

    float* cs = (float*)smem;   // [128][260]
    float* sb1s = (float*)(smem + 128 * 260 * 4);
    float* sw2s = sb1s + 128;
#pragma unroll
    for (int mt = 0; mt < 4; mt++) {
#pragma unroll
        for (int nt = 0; nt < 8; nt++) {
            const int r = wm * 64 + mt * 16 + qrow;
            const int c = wn * 64 + nt * 8 + (lane & 3) * 2;
            cs[r * 260 + c]           = acc[mt][nt][0];
            cs[r * 260 + c + 1]       = acc[mt][nt][1];
            cs[(r + 8) * 260 + c]     = acc[mt][nt][2];
            cs[(r + 8) * 260 + c + 1] = acc[mt][nt][3];
        }
    }
    if (EMIT == 5) {
        if (tid < 128) sb1s[tid] = sb1g[tid];
        else           sw2s[tid - 128] = sw2g[tid - 128];
    }
    __syncthreads();
    {
        const int row = tid >> 1;
        const int hf  = tid & 1;
        if (EMIT == 0) {
            const float4* srow = (const float4*)(cs + row * 260 + hf * 128);
            float4* crow = (float4*)(Cf + (m0 + row) * (long)ldc + n0 + hf * 128);
#pragma unroll
            for (int i = 0; i < 32; i++) crow[i] = srow[i];
        } else {  // EMIT == 5
            if ((int)blockIdx.x < 8) {
                const float4* srow = (const float4*)(cs + row * 260 + hf * 128);
                __half2* hrow = (__half2*)(Chi + (m0 + row) * (long)ldc + n0 + hf * 128);
#pragma unroll
                for (int i = 0; i < 32; i++) {
                    float4 v = srow[i];
                    hrow[2 * i]     = __halves2half2(__float2half_rn(v.x), __float2half_rn(v.y));
                    hrow[2 * i + 1] = __halves2half2(__float2half_rn(v.z), __float2half_rn(v.w));
                }
            } else {
                const float* crow = cs + row * 260 + hf * 128;
                float s = 0.f;
#pragma unroll
                for (int i = 0; i < 128; i++)
                    s += fmaxf(crow[i] + sb1s[i], 0.f) * sw2s[i];
                const long m = m0 + row;
                const int b = (int)(m >> 12);
                const int sq = (int)(m & 4095);
                const int h = ((int)blockIdx.x - 8) * 2 + hf;
                Cf[((long)(b * NHEADS + h)) * SS + sq] = s + sb2g[0];
            }
        }
    }
}

// =================== fused attention (unchanged) ===================
#define FA_STR  136
#define FA_PLNB (128 * FA_STR * 2)

__global__ __launch_bounds__(256, 1) void fused_attn(
    const __half* __restrict__ Qg, const __half* __restrict__ Kg,
    const __half* __restrict__ Vg, __half* __restrict__ Og, float scale)
{
    extern __shared__ char smem[];
    __half* Qp = (__half*)smem;
    __half* Kp = (__half*)(smem + FA_PLNB);
    __half* Vp = (__half*)(smem + 2 * FA_PLNB);
    float*  red = (float*)(smem + 3 * FA_PLNB);
    const int tid  = threadIdx.x;
    const int wid  = tid >> 5;
    const int lane = tid & 31;
    const int wm   = wid & 1;
    const int wn   = wid >> 1;
    const int qrow = lane >> 2;
    const int qk   = (lane & 3) * 2;

    const int bh = blockIdx.y, zb = bh >> 4, zh = bh & 15;
    const long m0 = (long)blockIdx.x * 128;

    const __half* Qsrc = Qg + ((long)zb * SS + m0) * HH + zh * HDIM;
    const __half* Ksrc = Kg + (long)bh * (KSEL * HDIM);
    const __half* Vsrc = Vg + (long)bh * (KSEL * HDIM);

#pragma unroll
    for (int e = 0; e < 8; e++) {
        int idx = tid + e * 256;
        int r = idx >> 4, s = idx & 15;
        ((uint4*)Qp)[r * 17 + s] = ((const uint4*)(Qsrc + (long)r * HH))[s];
        ((uint4*)Kp)[r * 17 + s] = ((const uint4*)(Ksrc + r * HDIM))[s];
        ((uint4*)Vp)[r * 17 + s] = ((const uint4*)(Vsrc + r * HDIM))[s];
    }
    __syncthreads();

    float acc[4][4][4];
#pragma unroll
    for (int i = 0; i < 4; i++)
#pragma unroll
        for (int j = 0; j < 4; j++)
#pragma unroll
            for (int r = 0; r < 4; r++) acc[i][j][r] = 0.f;
    {
        const uint32_t* pQ = (const uint32_t*)Qp;
        const uint32_t* pK = (const uint32_t*)Kp;
#pragma unroll
        for (int kc = 0; kc < 8; kc++) {
            const int kb = kc * 16;
            uint32_t af[4][4], bf[4][2];
#pragma unroll
            for (int mt = 0; mt < 4; mt++) {
                const int mr = wm * 64 + mt * 16 + qrow;
                af[mt][0] = pQ[(mr * FA_STR + kb + qk) >> 1];
                af[mt][1] = pQ[((mr + 8) * FA_STR + kb + qk) >> 1];
                af[mt][2] = pQ[(mr * FA_STR + kb + qk + 8) >> 1];
                af[mt][3] = pQ[((mr + 8) * FA_STR + kb + qk + 8) >> 1];
            }
#pragma unroll
            for (int nt = 0; nt < 4; nt++) {
                const int nr = wn * 32 + nt * 8 + qrow;
                bf[nt][0] = pK[(nr * FA_STR + kb + qk) >> 1];
                bf[nt][1] = pK[(nr * FA_STR + kb + qk + 8) >> 1];
            }
#pragma unroll
            for (int mt = 0; mt < 4; mt++)
#pragma unroll
                for (int nt = 0; nt < 4; nt++)
                    mma16816(acc[mt][nt], af[mt], bf[nt][0], bf[nt][1]);
        }
    }

    float rmax[8];
#pragma unroll
    for (int mt = 0; mt < 4; mt++) {
        float m0v = -1e30f, m1v = -1e30f;
#pragma unroll
        for (int nt = 0; nt < 4; nt++) {
            m0v = fmaxf(m0v, fmaxf(acc[mt][nt][0], acc[mt][nt][1]));
            m1v = fmaxf(m1v, fmaxf(acc[mt][nt][2], acc[mt][nt][3]));
        }
        rmax[mt * 2]     = m0v;
        rmax[mt * 2 + 1] = m1v;
    }
#pragma unroll
    for (int i = 0; i < 8; i++) {
        rmax[i] = fmaxf(rmax[i], __shfl_xor_sync(0xFFFFFFFFu, rmax[i], 1));
        rmax[i] = fmaxf(rmax[i], __shfl_xor_sync(0xFFFFFFFFu, rmax[i], 2));
    }
    if ((lane & 3) == 0) {
#pragma unroll
        for (int mt = 0; mt < 4; mt++) {
            red[(wm * 64 + mt * 16 + qrow) * 4 + wn]     = rmax[mt * 2];
            red[(wm * 64 + mt * 16 + qrow + 8) * 4 + wn] = rmax[mt * 2 + 1];
        }
    }
    __syncthreads();
#pragma unroll
    for (int mt = 0; mt < 4; mt++) {
        const int r0r = wm * 64 + mt * 16 + qrow;
        float g0 = fmaxf(fmaxf(red[r0r * 4], red[r0r * 4 + 1]), fmaxf(red[r0r * 4 + 2], red[r0r * 4 + 3]));
        const int r1r = r0r + 8;
        float g1 = fmaxf(fmaxf(red[r1r * 4], red[r1r * 4 + 1]), fmaxf(red[r1r * 4 + 2], red[r1r * 4 + 3]));
        rmax[mt * 2] = g0; rmax[mt * 2 + 1] = g1;
    }
    __syncthreads();
    float rsum[8];
#pragma unroll
    for (int i = 0; i < 8; i++) rsum[i] = 0.f;
#pragma unroll
    for (int mt = 0; mt < 4; mt++)
#pragma unroll
        for (int nt = 0; nt < 4; nt++) {
            acc[mt][nt][0] = expf(acc[mt][nt][0] * scale - rmax[mt * 2] * scale);
            acc[mt][nt][1] = expf(acc[mt][nt][1] * scale - rmax[mt * 2] * scale);
            acc[mt][nt][2] = expf(acc[mt][nt][2] * scale - rmax[mt * 2 + 1] * scale);
            acc[mt][nt][3] = expf(acc[mt][nt][3] * scale - rmax[mt * 2 + 1] * scale);
            rsum[mt * 2]     += acc[mt][nt][0] + acc[mt][nt][1];
            rsum[mt * 2 + 1] += acc[mt][nt][2] + acc[mt][nt][3];
        }
#pragma unroll
    for (int i = 0; i < 8; i++) {
        rsum[i] += __shfl_xor_sync(0xFFFFFFFFu, rsum[i], 1);
        rsum[i] += __shfl_xor_sync(0xFFFFFFFFu, rsum[i], 2);
    }
    if ((lane & 3) == 0) {
#pragma unroll
        for (int mt = 0; mt < 4; mt++) {
            red[(wm * 64 + mt * 16 + qrow) * 4 + wn]     = rsum[mt * 2];
            red[(wm * 64 + mt * 16 + qrow + 8) * 4 + wn] = rsum[mt * 2 + 1];
        }
    }
    __syncthreads();
#pragma unroll
    for (int mt = 0; mt < 4; mt++) {
        const int r0r = wm * 64 + mt * 16 + qrow;
        rsum[mt * 2]     = 1.0f / (red[r0r * 4] + red[r0r * 4 + 1] + red[r0r * 4 + 2] + red[r0r * 4 + 3]);
        const int r1r = r0r + 8;
        rsum[mt * 2 + 1] = 1.0f / (red[r1r * 4] + red[r1r * 4 + 1] + red[r1r * 4 + 2] + red[r1r * 4 + 3]);
    }
    __syncthreads();

#pragma unroll
    for (int mt = 0; mt < 4; mt++)
#pragma unroll
        for (int nt = 0; nt < 4; nt++) {
            const int r = wm * 64 + mt * 16 + qrow;
            const int c = wn * 32 + nt * 8 + qk;
            *(__half2*)(Qp + r * FA_STR + c) =
                __halves2half2(__float2half_rn(acc[mt][nt][0] * rsum[mt * 2]),
                               __float2half_rn(acc[mt][nt][1] * rsum[mt * 2]));
            *(__half2*)(Qp + (r + 8) * FA_STR + c) =
                __halves2half2(__float2half_rn(acc[mt][nt][2] * rsum[mt * 2 + 1]),
                               __float2half_rn(acc[mt][nt][3] * rsum[mt * 2 + 1]));
        }
    __syncthreads();

#pragma unroll
    for (int i = 0; i < 4; i++)
#pragma unroll
        for (int j = 0; j < 4; j++)
#pragma unroll
            for (int r = 0; r < 4; r++) acc[i][j][r] = 0.f;
    {
        const uint32_t* pP = (const uint32_t*)Qp;
        const uint32_t* pV = (const uint32_t*)Vp;
#pragma unroll
        for (int kc = 0; kc < 8; kc++) {
            const int kb = kc * 16;
            uint32_t af[4][4], bf[4][2];
#pragma unroll
            for (int mt = 0; mt < 4; mt++) {
                const int mr = wm * 64 + mt * 16 + qrow;
                af[mt][0] = pP[(mr * FA_STR + kb + qk) >> 1];
                af[mt][1] = pP[((mr + 8) * FA_STR + kb + qk) >> 1];
                af[mt][2] = pP[(mr * FA_STR + kb + qk + 8) >> 1];
                af[mt][3] = pP[((mr + 8) * FA_STR + kb + qk + 8) >> 1];
            }
#pragma unroll
            for (int nt = 0; nt < 4; nt++) {
                const int nr = wn * 32 + nt * 8 + qrow;
                bf[nt][0] = pV[(nr * FA_STR + kb + qk) >> 1];
                bf[nt][1] = pV[(nr * FA_STR + kb + qk + 8) >> 1];
            }
#pragma unroll
            for (int mt = 0; mt < 4; mt++)
#pragma unroll
                for (int nt = 0; nt < 4; nt++)
                    mma16816(acc[mt][nt], af[mt], bf[nt][0], bf[nt][1]);
        }
    }

#pragma unroll
    for (int mt = 0; mt < 4; mt++)
#pragma unroll
        for (int nt = 0; nt < 4; nt++) {
            const int r = wm * 64 + mt * 16 + qrow;
            const int c = wn * 32 + nt * 8 + qk;
            __half* dst0 = Og + ((long)zb * SS + m0 + r) * HH + zh * HDIM + c;
            __half* dst1 = Og + ((long)zb * SS + m0 + r + 8) * HH + zh * HDIM + c;
            *(__half2*)dst0 = __halves2half2(__float2half_rn(acc[mt][nt][0]), __float2half_rn(acc[mt][nt][1]));
            *(__half2*)dst1 = __halves2half2(__float2half_rn(acc[mt][nt][2]), __float2half_rn(acc[mt][nt][3]));
        }
}

// ---------------- sparsek projection + approx top-k + band ----------------
__device__ __forceinline__ unsigned enc_desc(float v) {
    unsigned b = __float_as_uint(v);
    unsigned o = (b & 0x80000000u) ? ~b : (b | 0x80000000u);
    return ~o;
}
__device__ __forceinline__ float dec_desc(unsigned d) {
    unsigned o = ~d;
    unsigned b = (o & 0x80000000u) ? (o ^ 0x80000000u) : ~o;
    return __uint_as_float(b);
}

__global__ __launch_bounds__(1024) void sparsek_topk(const float* __restrict__ scores,
                                                     int* __restrict__ out_idx,
                                                     int* __restrict__ band,
                                                     int* __restrict__ nposg)
{
    __shared__ unsigned long long key[SS];
    __shared__ unsigned char flag[SS];
    __shared__ float fred[32];
    __shared__ int   ired[32];
    __shared__ int   rho_s, npos_s;
    __shared__ float tau_s;
    int bh  = blockIdx.x;
    int tid = threadIdx.x;
    int lane = tid & 31, warp = tid >> 5;
    const float* s = scores + (long)bh * SS;

    for (int i = tid; i < SS; i += 1024)
        key[i] = ((unsigned long long)enc_desc(s[i]) << 32) | (unsigned)i;
    __syncthreads();

    for (int k = 2; k <= SS; k <<= 1) {
        for (int j = k >> 1; j > 0; j >>= 1) {
            for (int i = tid; i < SS; i += 1024) {
                int ixj = i ^ j;
                if (ixj > i) {
                    bool up = ((i & k) == 0);
                    unsigned long long a = key[i], b = key[ixj];
                    if ((a > b) == up) { key[i] = b; key[ixj] = a; }
                }
            }
            __syncthreads();
        }
    }

    if (tid < BAND)
        band[bh * BAND + tid] = (int)(key[tid] & 0xFFFFFFFFu);

    float v[4], pc[4];
#pragma unroll
    for (int j = 0; j < 4; j++) v[j] = dec_desc((unsigned)(key[tid * 4 + j] >> 32));
    pc[0] = v[0]; pc[1] = pc[0] + v[1]; pc[2] = pc[1] + v[2]; pc[3] = pc[2] + v[3];
    float tot = pc[3];
#pragma unroll
    for (int o = 1; o < 32; o <<= 1) {
        float n = __shfl_up_sync(0xFFFFFFFFu, tot, o);
        if (lane >= o) tot += n;
    }
    if (lane == 31) fred[warp] = tot;
    __syncthreads();
    if (warp == 0) {
        float w = fred[lane];
#pragma unroll
        for (int o = 1; o < 32; o <<= 1) {
            float n = __shfl_up_sync(0xFFFFFFFFu, w, o);
            if (lane >= o) w += n;
        }
        fred[lane] = w;
    }
    __syncthreads();
    const float base = (warp ? fred[warp - 1] : 0.f) + (tot - pc[3]);

    int cnt = 0;
#pragma unroll
    for (int j = 0; j < 4; j++) {
        float csj = base + pc[j];
        float thr = (csj - (float)KSEL) / (float)(tid * 4 + j + 1);
        if (v[j] > thr) cnt++;
    }
#pragma unroll
    for (int o = 16; o > 0; o >>= 1) cnt += __shfl_xor_sync(0xFFFFFFFFu, cnt, o);
    if (lane == 0) ired[warp] = cnt;
    __syncthreads();
    if (tid == 0) {
        int r = 0;
#pragma unroll
        for (int i = 0; i < 32; i++) r += ired[i];
        rho_s = (r < 1) ? 1 : r;
    }
    __syncthreads();
    const int rho = rho_s;
    {
        int rr = rho - 1;
        if ((rr >> 2) == tid)
            tau_s = (base + pc[rr & 3] - (float)KSEL) / (float)rho;
    }
    __syncthreads();
    const float tau = tau_s;
    int cnp = 0;
#pragma unroll
    for (int j = 0; j < 4; j++) if (v[j] > tau) cnp++;
#pragma unroll
    for (int o = 16; o > 0; o >>= 1) cnp += __shfl_xor_sync(0xFFFFFFFFu, cnp, o);
    if (lane == 0) ired[warp] = cnp;
    __syncthreads();
    if (tid == 0) {
        int r = 0;
#pragma unroll
        for (int i = 0; i < 32; i++) r += ired[i];
        npos_s = r;
        nposg[bh] = r;
    }
    __syncthreads();

    const int npos = npos_s;
    if (npos >= KSEL) {
        if (tid < KSEL)
            out_idx[bh * KSEL + tid] = (int)(key[tid] & 0xFFFFFFFFu);
    } else {
        if (tid < npos)
            out_idx[bh * KSEL + tid] = (int)(key[tid] & 0xFFFFFFFFu);
        for (int i = tid; i < SS; i += 1024) flag[i] = 0;
        __syncthreads();
        for (int i = tid; i < npos; i += 1024)
            flag[key[i] & 0xFFFFFFFFu] = 1;
        __syncthreads();
        if (tid == 0) {
            int c2 = npos;
            for (int i = 0; i < SS && c2 < KSEL; i++)
                if (!flag[i]) out_idx[bh * KSEL + c2++] = i;
        }
    }
}

// ---------------- merge: exact top-128 from rescored band ----------------
__global__ __launch_bounds__(256) void merge_band(const float* __restrict__ sc,
                                                  const int* __restrict__ band,
                                                  const int* __restrict__ nposg,
                                                  int* __restrict__ out_idx)
{
    __shared__ unsigned long long key[BAND];
    int bh = blockIdx.x, t = threadIdx.x;
    key[t] = ((unsigned long long)enc_desc(sc[bh * BAND + t]) << 32)
           | (unsigned)band[bh * BAND + t];
    __syncthreads();
    for (int k = 2; k <= BAND; k <<= 1) {
        for (int j = k >> 1; j > 0; j >>= 1) {
            int ixj = t ^ j;
            if (ixj > t) {
                bool up = ((t & k) == 0);
                unsigned long long a = key[t], b = key[ixj];
                if ((a > b) == up) { key[t] = b; key[ixj] = a; }
            }
            __syncthreads();
        }
    }
    if (nposg[bh] >= KSEL && t < KSEL)
        out_idx[bh * KSEL + t] = (int)(key[t] & 0xFFFFFFFFu);
}

// ---------------- launch ----------------
extern "C" void kernel_launch(void* const* d_in, const int* in_sizes, int n_in,
                              void* d_out, int out_size)
{
    const float* x   = (const float*)d_in[0];
    const float* wq  = (const float*)d_in[1];
    const float* wk  = (const float*)d_in[2];
    const float* wv  = (const float*)d_in[3];
    const float* wo  = (const float*)d_in[4];
    const float* sw1 = (const float*)d_in[5];
    const float* sb1 = (const float*)d_in[6];
    const float* sw2 = (const float*)d_in[7];
    const float* sb2 = (const float*)d_in[8];
    float* out = (float*)d_out;

    float *pScores, *pS256;
    int *pIdx, *pBand, *pNpos;
    __half *pXhi, *pXlo, *pQhi, *pOhi;
    __half *pWBig, *pWk, *pWv, *pWo, *pWchi, *pWclo, *pKselh, *pVselTh;
    cudaGetSymbolAddress((void**)&pScores, gScores);
    cudaGetSymbolAddress((void**)&pS256,   gS256);
    cudaGetSymbolAddress((void**)&pIdx,    gIdx);
    cudaGetSymbolAddress((void**)&pBand,   gBand);
    cudaGetSymbolAddress((void**)&pNpos,   gNpos);
    cudaGetSymbolAddress((void**)&pXhi,    gXhi);
    cudaGetSymbolAddress((void**)&pXlo,    gXlo);
    cudaGetSymbolAddress((void**)&pQhi,    gQhi);
    cudaGetSymbolAddress((void**)&pOhi,    gOhi);
    cudaGetSymbolAddress((void**)&pWBig,   gWBig);
    cudaGetSymbolAddress((void**)&pWk,     gWk);
    cudaGetSymbolAddress((void**)&pWv,     gWv);
    cudaGetSymbolAddress((void**)&pWo,     gWo);
    cudaGetSymbolAddress((void**)&pWchi,   gWchi);
    cudaGetSymbolAddress((void**)&pWclo,   gWclo);
    cudaGetSymbolAddress((void**)&pKselh,  gKselh);
    cudaGetSymbolAddress((void**)&pVselTh, gVselTh);

    const int SM12 = 67584;
    const int SM33 = 81920;
    const int SMW  = 128 * 260 * 4 + 1024;   // 134144
    const int SMA  = 3 * FA_PLNB + 128 * 4 * 4;
    cudaFuncSetAttribute(hgemm_w<0>, cudaFuncAttributeMaxDynamicSharedMemorySize, SMW);
    cudaFuncSetAttribute(hgemm_w<5>, cudaFuncAttributeMaxDynamicSharedMemorySize, SMW);
    cudaFuncSetAttribute(hgemm<1,2,1>, cudaFuncAttributeMaxDynamicSharedMemorySize, SM12);
    cudaFuncSetAttribute(hgemm<1,2,2>, cudaFuncAttributeMaxDynamicSharedMemorySize, SM12);
    cudaFuncSetAttribute(hgemm<3,3,1>, cudaFuncAttributeMaxDynamicSharedMemorySize, SM33);
    cudaFuncSetAttribute(fused_attn, cudaFuncAttributeMaxDynamicSharedMemorySize, SMA);

    const long sSelh = (long)KSEL * HDIM;
    const long sWh   = (long)HDIM * HH;

    dim3 gMerged(2 * HH / 256, NROWS / 128, 1);  // (16, 64)
    dim3 gWo(HH / 256, NROWS / 128, 1);          // (8, 64) 128x256 tiles
    dim3 gResc(1, BAND / 128, NBH);              // (1, 2, 32)
    dim3 gSel(1, 1, NBH);                        // (1, 1, 32)
    dim3 gFA(SS / 128, NBH);                     // (32, 32)

    // ---- splits + composed score weight ----
    splitX<<<(int)((ROWHID / 8 + 255) / 256), 256>>>(x, pXhi, pXlo, ROWHID / 8);
    splitW<<<(int)((WN / 8 + 255) / 256), 256>>>(wq, wk, wv, wo, pWBig, pWk, pWv, pWo);
    wc_make<<<16 * 64, 256>>>(sw1, wk, pWchi, pWclo, pWBig);

    // ---- merged: Q = X@wq^T  +  approx scores = head(X@Wc^T) ----
    hgemm_w<5><<<gMerged, 256, SMW>>>(pXhi, pWBig, pScores, pQhi, HH, HH, HH, HH,
                                      sb1, sw2, sb2);

    // ---- sort + sparsek stats + candidate band ----
    sparsek_topk<<<NBH, 1024>>>(pScores, pIdx, pBand, pNpos);

    // ---- rescore band exactly (3-prod composed, A rows indexed into X) ----
    hgemm<3,3,1><<<gResc, 256, SM33>>>(pXhi, pXlo, pWchi, pWclo, pS256, nullptr,
                                       HH, HH, 1,
                                       0, 0, 0, sWh, (long)NHEADS * BAND, (long)BAND,
                                       HH, 1.0f, sb1, sw2, sb2,
                                       pBand, BAND);
    merge_band<<<NBH, 256>>>(pS256, pBand, pNpos, pIdx);

    // ---- Ksel = Xsel @ wk_head^T (A indexed), VselT = wv_head @ Xsel^T (B indexed) ----
    hgemm<1,2,1><<<gSel, 256, SM12>>>(pXhi, nullptr, pWk, nullptr, nullptr, pKselh,
                                      HH, HH, HDIM,
                                      0, 0, 0, sWh,
                                      (long)NHEADS * KSEL * HDIM, sSelh,
                                      HH, 1.0f, nullptr, nullptr, nullptr,
                                      pIdx, KSEL);
    hgemm<1,2,2><<<gSel, 256, SM12>>>(pWv, nullptr, pXhi, nullptr, nullptr, pVselTh,
                                      HH, HH, KSEL,
                                      0, sWh, 0, 0,
                                      (long)NHEADS * KSEL * HDIM, sSelh,
                                      HH, 1.0f, nullptr, nullptr, nullptr,
                                      pIdx, KSEL);

    // ---- fused attention ----
    const float scale = 0.08838834764831845f;
    fused_attn<<<gFA, 256, SMA>>>(pQhi, pKselh, pVselTh, pOhi, scale);

    // ---- out = O @ wo^T (1-prod, 128x256 tiles, fp32 out) ----
    hgemm_w<0><<<gWo, 256, SMW>>>(pOhi, pWo, out, nullptr, HH, HH, HH, HH,
                                  nullptr, nullptr, nullptr);
}